// round 2
// baseline (speedup 1.0000x reference)
#include <cuda_runtime.h>
#include <cstdint>
#include <math.h>

// Problem constants
#define NLAYERS 2
#define NMAT    4
#define NMULTI  8
#define NE      9          // NMULTI + 1 experts
#define D       128
#define NTOK    65536      // T*B = 2048*32
#define TILE_M  32
#define KC      32
#define NBLK    (NTOK / TILE_M + NE)   // 2057: worst-case padded tiles
#define INVALID 0xFFFFFFFFu

// ---------------- device scratch (no allocations allowed) ----------------
__device__ unsigned int g_counts[NE];
__device__ unsigned int g_cursor[NE];
__device__ unsigned int g_off[NE];
__device__ unsigned int g_list[NBLK * TILE_M];

// ---------------- prep kernels: group tokens by expert ----------------
__global__ void prep_zero() {
    int stride = gridDim.x * blockDim.x;
    for (int i = blockIdx.x * blockDim.x + threadIdx.x; i < NBLK * TILE_M; i += stride)
        g_list[i] = INVALID;
    if (blockIdx.x == 0 && threadIdx.x < NE) {
        g_counts[threadIdx.x] = 0;
        g_cursor[threadIdx.x] = 0;
    }
}

__global__ void prep_hist(const int* __restrict__ pos) {
    __shared__ unsigned int h[NE];
    if (threadIdx.x < NE) h[threadIdx.x] = 0;
    __syncthreads();
    int t = blockIdx.x * blockDim.x + threadIdx.x;   // grid sized exactly NTOK
    int e = min(pos[t], NMULTI);
    atomicAdd(&h[e], 1u);
    __syncthreads();
    if (threadIdx.x < NE) atomicAdd(&g_counts[threadIdx.x], h[threadIdx.x]);
}

__global__ void prep_off() {
    unsigned int o = 0;
    for (int e = 0; e < NE; e++) {
        g_off[e] = o;
        o += ((g_counts[e] + TILE_M - 1) / TILE_M) * TILE_M;
    }
}

__global__ void prep_scatter(const int* __restrict__ pos) {
    __shared__ unsigned int sc[NE];
    __shared__ unsigned int sb[NE];
    if (threadIdx.x < NE) sc[threadIdx.x] = 0;
    __syncthreads();
    int t = blockIdx.x * blockDim.x + threadIdx.x;
    int e = min(pos[t], NMULTI);
    unsigned int my = atomicAdd(&sc[e], 1u);
    __syncthreads();
    if (threadIdx.x < NE) sb[threadIdx.x] = atomicAdd(&g_cursor[threadIdx.x], sc[threadIdx.x]);
    __syncthreads();
    g_list[g_off[e] + sb[e] + my] = (unsigned int)t;
}

// ---------------- main fused kernel ----------------
struct Smem {
    float Xs[TILE_M][D];        // 16 KB  — token tile, lives across both layers
    float Wc[NMAT][KC][D];      // 64 KB  — current K-chunk of all 4 matrices
    float Bs[NMAT][D];          // 2  KB  — biases for current layer
    unsigned int tok[TILE_M];
    unsigned int first;
    int expert;
};

__device__ __forceinline__ float sigm(float x) {
    return 1.0f / (1.0f + expf(-x));
}

__global__ __launch_bounds__(256, 2) void mpt_main(
    const int* __restrict__ pos,
    const float* __restrict__ X0,
    const float* __restrict__ W,     // [NLAYERS][NMAT][NE][D][D]
    const float* __restrict__ Bv,    // [NLAYERS][NMAT][NE][D]
    float* __restrict__ Out)
{
    extern __shared__ char raw[];
    Smem& s = *reinterpret_cast<Smem*>(raw);
    const int tid = threadIdx.x;

    if (tid < TILE_M) s.tok[tid] = g_list[blockIdx.x * TILE_M + tid];
    __syncthreads();
    if (tid == 0) {
        unsigned int ft = INVALID;
        #pragma unroll
        for (int r = 0; r < TILE_M; r++) {
            if (s.tok[r] != INVALID) { ft = s.tok[r]; break; }
        }
        s.first = ft;
        s.expert = (ft == INVALID) ? -1 : min(pos[ft], NMULTI);
    }
    __syncthreads();
    const int e = s.expert;
    if (e < 0) return;                 // fully padded tile
    const unsigned int first = s.first;

    // gather X tile (invalid rows read a safe duplicate row; never written out)
    for (int i = tid; i < TILE_M * (D / 4); i += 256) {
        int r = i >> 5;
        int c = i & 31;
        unsigned int t = s.tok[r];
        if (t == INVALID) t = first;
        float4 v = reinterpret_cast<const float4*>(X0 + (size_t)t * D)[c];
        reinterpret_cast<float4*>(&s.Xs[r][0])[c] = v;
    }

    const int lane_c = tid & 31;            // column group: cols 4*lane_c..+3
    const int warp_r = (tid >> 5) * 4;      // rows warp_r..warp_r+3 (warp-uniform)
    const int col0   = lane_c * 4;

    float nx[4][4];

    for (int l = 0; l < NLAYERS; l++) {
        __syncthreads();   // Xs ready / previous layer's gating (Bs reads) complete

        // biases for this layer's 4 matrices
        for (int i = tid; i < NMAT * D; i += 256) {
            int j = i >> 7;
            int f = i & 127;
            s.Bs[j][f] = Bv[((size_t)(l * NMAT + j) * NE + e) * D + f];
        }

        float acc[NMAT][4][4];
        #pragma unroll
        for (int j = 0; j < NMAT; j++)
            #pragma unroll
            for (int i = 0; i < 4; i++)
                #pragma unroll
                for (int f = 0; f < 4; f++) acc[j][i][f] = 0.0f;

        const float* Wb0 = W + ((size_t)(l * NMAT) * NE + e) * D * D;
        const size_t jstride = (size_t)NE * D * D;

        for (int kc = 0; kc < D / KC; kc++) {
            __syncthreads();   // previous chunk fully consumed
            // load chunk: 4 mats x 32 k x 128 f  (16 float4 per thread, coalesced)
            for (int i = tid; i < NMAT * KC * (D / 4); i += 256) {
                int j   = i >> 10;          // KC*D/4 = 1024
                int rem = i & 1023;
                int k   = rem >> 5;
                int c   = rem & 31;
                const float4* src = reinterpret_cast<const float4*>(
                    Wb0 + (size_t)j * jstride + (size_t)(kc * KC + k) * D);
                reinterpret_cast<float4*>(&s.Wc[j][k][0])[c] = src[c];
            }
            __syncthreads();

            #pragma unroll 8
            for (int k = 0; k < KC; k++) {
                float xv[4];
                #pragma unroll
                for (int i = 0; i < 4; i++)
                    xv[i] = s.Xs[warp_r + i][kc * KC + k];   // warp-uniform broadcast
                #pragma unroll
                for (int j = 0; j < NMAT; j++) {
                    float4 w = reinterpret_cast<const float4*>(&s.Wc[j][k][0])[lane_c];
                    #pragma unroll
                    for (int i = 0; i < 4; i++) {
                        acc[j][i][0] += xv[i] * w.x;
                        acc[j][i][1] += xv[i] * w.y;
                        acc[j][i][2] += xv[i] * w.z;
                        acc[j][i][3] += xv[i] * w.w;
                    }
                }
            }
        }
        __syncthreads();   // all GEMM reads of Xs complete before Xs update

        // gating (each thread owns its 4x4 output tile exclusively)
        #pragma unroll
        for (int i = 0; i < 4; i++) {
            #pragma unroll
            for (int f = 0; f < 4; f++) {
                int col = col0 + f;
                float xv = s.Xs[warp_r + i][col];
                float sf = acc[0][i][f] + s.Bs[0][col];
                float lg = acc[1][i][f] + s.Bs[1][col];
                float lf = acc[2][i][f] + s.Bs[2][col];
                float of = acc[3][i][f] + s.Bs[3][col];
                float nr = xv * sigm(sf) + tanhf(lg) * sigm(lf);
                nx[i][f] = tanhf(nr) * sigm(of);
            }
        }
        #pragma unroll
        for (int i = 0; i < 4; i++)
            *reinterpret_cast<float4*>(&s.Xs[warp_r + i][col0]) =
                make_float4(nx[i][0], nx[i][1], nx[i][2], nx[i][3]);
    }

    // write output from final-layer registers (coalesced float4 per row)
    #pragma unroll
    for (int i = 0; i < 4; i++) {
        unsigned int t = s.tok[warp_r + i];
        if (t != INVALID) {
            reinterpret_cast<float4*>(Out + (size_t)t * D)[lane_c] =
                make_float4(nx[i][0], nx[i][1], nx[i][2], nx[i][3]);
        }
    }
}

// ---------------- launch ----------------
extern "C" void kernel_launch(void* const* d_in, const int* in_sizes, int n_in,
                              void* d_out, int out_size)
{
    const int*   pos = (const int*)d_in[0];     // positions [T,B] (int32 in harness)
    const float* X0  = (const float*)d_in[1];   // outputs   [T,B,D]
    const float* W   = (const float*)d_in[2];   // Ws [2,4,9,D,D]
    const float* Bv  = (const float*)d_in[3];   // bs [2,4,9,D]
    float*       Out = (float*)d_out;

    (void)in_sizes; (void)n_in; (void)out_size;

    cudaFuncSetAttribute(mpt_main, cudaFuncAttributeMaxDynamicSharedMemorySize,
                         (int)sizeof(Smem));

    prep_zero<<<64, 256>>>();
    prep_hist<<<NTOK / 256, 256>>>(pos);
    prep_off<<<1, 1>>>();
    prep_scatter<<<NTOK / 256, 256>>>(pos);
    mpt_main<<<NBLK, 256, sizeof(Smem)>>>(pos, X0, W, Bv, Out);
}

// round 4
// speedup vs baseline: 1.9649x; 1.9649x over previous
#include <cuda_runtime.h>
#include <cstdint>

#define NLAYERS 2
#define NMAT 4
#define NE 9
#define D 128
#define NTOK 65536
#define TILE_M 128
#define NBLK (NTOK / TILE_M + NE)     // 521
#define INVALID 0xFFFFFFFFu

#define PADX 132                       // Xs row stride (floats) — conflict-free frags
#define PADW 36                        // W slab row stride (floats)
#define SLAB_FLOATS (NMAT * D * PADW)  // 18432 floats = 73728 B per buffer

#define OFF_TOK  0
#define OFF_BIAS 512
#define OFF_X    2560
#define OFF_W    (OFF_X + TILE_M * PADX * 4)          // 70144
#define SMEM_TOTAL (OFF_W + 2 * SLAB_FLOATS * 4)      // 217600 B

// ---------------- device scratch ----------------
__device__ unsigned g_counts[NE];
__device__ unsigned g_cursor[NE];
__device__ unsigned g_off[NE];
__device__ unsigned g_list[NBLK * TILE_M];
__device__ float g_Wt[NLAYERS * NMAT * NE * D * D];   // tf32-rounded weights (same layout)

// ---------------- helpers ----------------
__device__ __forceinline__ float to_tf32(float x) {
    uint32_t u; asm("cvt.rna.tf32.f32 %0, %1;" : "=r"(u) : "f"(x));
    return __uint_as_float(u);
}
__device__ __forceinline__ float ex2a(float x) {
    float r; asm("ex2.approx.f32 %0, %1;" : "=f"(r) : "f"(x)); return r;
}
__device__ __forceinline__ float rcpa(float x) {
    float r; asm("rcp.approx.f32 %0, %1;" : "=f"(r) : "f"(x)); return r;
}
__device__ __forceinline__ float sigm(float v) {
    return rcpa(1.0f + ex2a(-1.4426950408889634f * v));
}
__device__ __forceinline__ float tanh_(float v) {
    return fmaf(2.0f, rcpa(1.0f + ex2a(-2.8853900817779268f * v)), -1.0f);
}
__device__ __forceinline__ void mma8(float* d, const uint32_t* a, uint32_t b0, uint32_t b1) {
    asm volatile(
        "mma.sync.aligned.m16n8k8.row.col.f32.tf32.tf32.f32 "
        "{%0,%1,%2,%3}, {%4,%5,%6,%7}, {%8,%9}, {%0,%1,%2,%3};"
        : "+f"(d[0]), "+f"(d[1]), "+f"(d[2]), "+f"(d[3])
        : "r"(a[0]), "r"(a[1]), "r"(a[2]), "r"(a[3]), "r"(b0), "r"(b1));
}
__device__ __forceinline__ void cpa16(uint32_t dst, const float* src) {
    asm volatile("cp.async.cg.shared.global [%0], [%1], 16;"
                 :: "r"(dst), "l"(__cvta_generic_to_global(src)) : "memory");
}

// ---------------- prep kernels ----------------
__global__ void prep_zero() {
    int stride = gridDim.x * blockDim.x;
    for (int i = blockIdx.x * blockDim.x + threadIdx.x; i < NBLK * TILE_M; i += stride)
        g_list[i] = INVALID;
    if (blockIdx.x == 0 && threadIdx.x < NE) {
        g_counts[threadIdx.x] = 0;
        g_cursor[threadIdx.x] = 0;
    }
}
__global__ void prep_hist(const int* __restrict__ pos) {
    __shared__ unsigned h[NE];
    if (threadIdx.x < NE) h[threadIdx.x] = 0;
    __syncthreads();
    int t = blockIdx.x * blockDim.x + threadIdx.x;
    int e = min(pos[t], NE - 1);
    atomicAdd(&h[e], 1u);
    __syncthreads();
    if (threadIdx.x < NE) atomicAdd(&g_counts[threadIdx.x], h[threadIdx.x]);
}
__global__ void prep_off() {
    unsigned o = 0;
    for (int e = 0; e < NE; e++) {
        g_off[e] = o;
        o += ((g_counts[e] + TILE_M - 1) / TILE_M) * TILE_M;
    }
}
__global__ void prep_scatter(const int* __restrict__ pos) {
    __shared__ unsigned sc[NE];
    __shared__ unsigned sb[NE];
    if (threadIdx.x < NE) sc[threadIdx.x] = 0;
    __syncthreads();
    int t = blockIdx.x * blockDim.x + threadIdx.x;
    int e = min(pos[t], NE - 1);
    unsigned my = atomicAdd(&sc[e], 1u);
    __syncthreads();
    if (threadIdx.x < NE) sb[threadIdx.x] = atomicAdd(&g_cursor[threadIdx.x], sc[threadIdx.x]);
    __syncthreads();
    g_list[g_off[e] + sb[e] + my] = (unsigned)t;
}
__global__ void prep_round(const float* __restrict__ W) {
    int i = blockIdx.x * blockDim.x + threadIdx.x;   // grid covers exactly the array
    g_Wt[i] = to_tf32(W[i]);
}

// ---------------- main kernel ----------------
__global__ __launch_bounds__(256, 1) void mpt_main(
    const int* __restrict__ pos,
    const float* __restrict__ X0,
    const float* __restrict__ Bv,
    float* __restrict__ Out)
{
    extern __shared__ __align__(16) char sm[];
    unsigned* s_tok = (unsigned*)(sm + OFF_TOK);
    float* Bs = (float*)(sm + OFF_BIAS);
    float* Xs = (float*)(sm + OFF_X);
    float* Ws = (float*)(sm + OFF_W);
    const uint32_t smW = (uint32_t)__cvta_generic_to_shared(sm + OFF_W);
    const int tid = threadIdx.x;

    if (tid < TILE_M) s_tok[tid] = g_list[blockIdx.x * TILE_M + tid];
    __syncthreads();
    const unsigned tok0 = s_tok[0];
    if (tok0 == INVALID) return;
    const int e = min(pos[tok0], NE - 1);

    // prologue: prefetch (l=0, cg=0) into buffer 0
    {
        #pragma unroll
        for (int i = 0; i < 16; i++) {
            int idx = tid + i * 256;
            int m = idx >> 10, rem = idx & 1023, k = rem >> 3, c8 = rem & 7;
            const float* src = g_Wt + ((size_t)m * NE + e) * (D * D) + k * D + c8 * 4;
            cpa16(smW + m * (D * PADW * 4) + k * (PADW * 4) + c8 * 16, src);
        }
        asm volatile("cp.async.commit_group;" ::: "memory");
    }

    // gather X tile (tf32-rounded) into padded SMEM
    for (int i = tid; i < TILE_M * 32; i += 256) {
        int r = i >> 5, c = i & 31;
        unsigned t = s_tok[r];
        if (t == INVALID) t = tok0;
        float4 v = reinterpret_cast<const float4*>(X0 + (size_t)t * D)[c];
        v.x = to_tf32(v.x); v.y = to_tf32(v.y); v.z = to_tf32(v.z); v.w = to_tf32(v.w);
        *reinterpret_cast<float4*>(Xs + (size_t)r * PADX + c * 4) = v;
    }

    const int lane = tid & 31, w = tid >> 5;
    const int lk = lane & 3, ln = lane >> 2;
    const int row0 = w * 16 + ln;

    float nxs[4][16];
    int buf = 0;

    #pragma unroll 1
    for (int l = 0; l < NLAYERS; l++) {
        for (int i = tid; i < NMAT * D; i += 256)
            Bs[i] = Bv[((size_t)(l * NMAT + (i >> 7)) * NE + e) * D + (i & 127)];

        #pragma unroll
        for (int cg = 0; cg < 4; cg++) {
            asm volatile("cp.async.wait_group 0;" ::: "memory");
            __syncthreads();   // slab ready; prev cg's reads of other buffer done; Xs visible
            int g = l * 4 + cg;
            if (g < 7) {
                int nl = (g + 1) >> 2, ncg = (g + 1) & 3;
                uint32_t dbase = smW + (buf ^ 1) * (SLAB_FLOATS * 4);
                #pragma unroll
                for (int i = 0; i < 16; i++) {
                    int idx = tid + i * 256;
                    int m = idx >> 10, rem = idx & 1023, k = rem >> 3, c8 = rem & 7;
                    const float* src = g_Wt + ((size_t)(nl * NMAT + m) * NE + e) * (D * D)
                                       + k * D + ncg * 32 + c8 * 4;
                    cpa16(dbase + m * (D * PADW * 4) + k * (PADW * 4) + c8 * 16, src);
                }
                asm volatile("cp.async.commit_group;" ::: "memory");
            }

            // ---- GEMM: 128 rows x 32 cols x 128 k, 4 matrices ----
            float acc[4][4][4];
            #pragma unroll
            for (int m = 0; m < 4; m++)
                #pragma unroll
                for (int nt = 0; nt < 4; nt++)
                    #pragma unroll
                    for (int c = 0; c < 4; c++) acc[m][nt][c] = 0.0f;

            const uint32_t* xa0 = (const uint32_t*)(Xs + row0 * PADX + lk);
            const uint32_t* xa1 = xa0 + 8 * PADX;
            const uint32_t* bb  = (const uint32_t*)(Ws + buf * SLAB_FLOATS + lk * PADW + ln);

            #pragma unroll 2
            for (int ks = 0; ks < 16; ks++) {
                uint32_t a[4];
                a[0] = xa0[ks * 8];
                a[1] = xa1[ks * 8];
                a[2] = xa0[ks * 8 + 4];
                a[3] = xa1[ks * 8 + 4];
                const uint32_t* bk = bb + ks * 8 * PADW;
                #pragma unroll
                for (int m = 0; m < 4; m++) {
                    const uint32_t* bm = bk + m * D * PADW;
                    #pragma unroll
                    for (int nt = 0; nt < 4; nt++) {
                        uint32_t b0 = bm[nt * 8];
                        uint32_t b1 = bm[nt * 8 + 4 * PADW];
                        mma8(acc[m][nt], a, b0, b1);
                    }
                }
            }

            // ---- gating, stash in registers ----
            const float* xg0 = Xs + row0 * PADX + cg * 32 + lk * 2;
            #pragma unroll
            for (int nt = 0; nt < 4; nt++) {
                #pragma unroll
                for (int h = 0; h < 2; h++) {
                    const float* xr = xg0 + h * 8 * PADX + nt * 8;
                    int col = cg * 32 + nt * 8 + lk * 2;
                    #pragma unroll
                    for (int c = 0; c < 2; c++) {
                        float sf = acc[0][nt][h * 2 + c] + Bs[0 * D + col + c];
                        float lg = acc[1][nt][h * 2 + c] + Bs[1 * D + col + c];
                        float lf = acc[2][nt][h * 2 + c] + Bs[2 * D + col + c];
                        float of = acc[3][nt][h * 2 + c] + Bs[3 * D + col + c];
                        float xv = xr[c];
                        float nr = xv * sigm(sf) + tanh_(lg) * sigm(lf);
                        nxs[cg][nt * 4 + h * 2 + c] = tanh_(nr) * sigm(of);
                    }
                }
            }
            buf ^= 1;
        }

        __syncthreads();   // all GEMM/gating reads of old Xs complete
        #pragma unroll
        for (int cg = 0; cg < 4; cg++) {
            #pragma unroll
            for (int nt = 0; nt < 4; nt++) {
                #pragma unroll
                for (int h = 0; h < 2; h++) {
                    float v0 = nxs[cg][nt * 4 + h * 2 + 0];
                    float v1 = nxs[cg][nt * 4 + h * 2 + 1];
                    if (l == 0) { v0 = to_tf32(v0); v1 = to_tf32(v1); }
                    *reinterpret_cast<float2*>(Xs + (row0 + h * 8) * PADX
                                               + cg * 32 + nt * 8 + lk * 2) =
                        make_float2(v0, v1);
                }
            }
        }
        __syncthreads();
    }

    // coalesced store of final X
    for (int i = tid; i < TILE_M * 32; i += 256) {
        int r = i >> 5, c = i & 31;
        unsigned t = s_tok[r];
        if (t != INVALID) {
            float4 v = *reinterpret_cast<const float4*>(Xs + (size_t)r * PADX + c * 4);
            reinterpret_cast<float4*>(Out + (size_t)t * D)[c] = v;
        }
    }
}

// ---------------- launch ----------------
extern "C" void kernel_launch(void* const* d_in, const int* in_sizes, int n_in,
                              void* d_out, int out_size)
{
    const int*   pos = (const int*)d_in[0];
    const float* X0  = (const float*)d_in[1];
    const float* W   = (const float*)d_in[2];
    const float* Bv  = (const float*)d_in[3];
    float*       Out = (float*)d_out;
    (void)in_sizes; (void)n_in; (void)out_size;

    cudaFuncSetAttribute(mpt_main, cudaFuncAttributeMaxDynamicSharedMemorySize, SMEM_TOTAL);

    prep_zero<<<64, 256>>>();
    prep_hist<<<NTOK / 256, 256>>>(pos);
    prep_off<<<1, 1>>>();
    prep_scatter<<<NTOK / 256, 256>>>(pos);
    prep_round<<<(NLAYERS * NMAT * NE * D * D) / 256, 256>>>(W);
    mpt_main<<<NBLK, 256, SMEM_TOTAL>>>(pos, X0, Bv, Out);
}